// round 4
// baseline (speedup 1.0000x reference)
#include <cuda_runtime.h>
#include <cuda_bf16.h>
#include <math.h>
#include <stdint.h>

#define TSTEPS 128
#define NENV   64
#define HID    1024
#define HID3   (3 * HID)
#define GK     3072     // split-K concat (3 * HID)

#define G      128      // persistent scan CTAs
#define JPC    8        // j per CTA
#define CK     128      // h k-chunk
#define HROW   (CK + 4)
#define WROW   (HID + 4)

// ---------------- scratch ----------------
__device__ float g_gi[TSTEPS * NENV * HID3];            // 96 MB
__device__ float g_ys[TSTEPS * NENV * HID];             // 32 MB
__device__ float g_h[2][NENV * HID];
__device__ unsigned g_count;
__device__ __nv_bfloat16 g_bufA[TSTEPS * NENV * GK];    // 48 MB: split A (x, then ys)
__device__ __nv_bfloat16 g_bufB[HID3 * GK];             // 18 MB: split B (w_ih, then w_out)

// ---------------- ptx helpers (sm_103-safe: no tcgen05) ----------------
__device__ __forceinline__ uint32_t smem_u32(const void* p) {
    uint32_t a;
    asm("{ .reg .u64 t; cvta.to.shared.u64 t, %1; cvt.u32.u64 %0, t; }" : "=r"(a) : "l"(p));
    return a;
}
#define SWZ128(x) ((x) ^ (((x) >> 3) & 0x70))

#define CP16(dst, src) \
    asm volatile("cp.async.cg.shared.global [%0], [%1], 16;" :: "r"(dst), "l"(src))
#define CP_COMMIT() asm volatile("cp.async.commit_group;" ::: "memory")
#define CP_WAIT2()  asm volatile("cp.async.wait_group 2;" ::: "memory")

#define LDSM4(r0, r1, r2, r3, addr) \
    asm volatile("ldmatrix.sync.aligned.m8n8.x4.shared.b16 {%0,%1,%2,%3}, [%4];" \
        : "=r"(r0), "=r"(r1), "=r"(r2), "=r"(r3) : "r"(addr))

#define MMA16816(d, a0, a1, a2, a3, b0, b1) \
    asm volatile("mma.sync.aligned.m16n8k16.row.col.f32.bf16.bf16.f32 " \
        "{%0,%1,%2,%3}, {%4,%5,%6,%7}, {%8,%9}, {%0,%1,%2,%3};" \
        : "+f"((d)[0]), "+f"((d)[1]), "+f"((d)[2]), "+f"((d)[3]) \
        : "r"(a0), "r"(a1), "r"(a2), "r"(a3), "r"(b0), "r"(b1))

// ---------------- misc ----------------
__device__ __forceinline__ float sigmoidf_(float x) { return 1.0f / (1.0f + expf(-x)); }
__device__ __forceinline__ void fma2(unsigned long long& c, unsigned long long a,
                                     unsigned long long b) {
    asm("fma.rn.f32x2 %0, %1, %2, %0;" : "+l"(c) : "l"(a), "l"(b));
}
__device__ __forceinline__ float lohi(unsigned long long v) {
    return __uint_as_float((unsigned)v) + __uint_as_float((unsigned)(v >> 32));
}

// ---------------- init / copy / split ----------------
__global__ void init_kernel(const float* __restrict__ hxs) {
    int i = blockIdx.x * blockDim.x + threadIdx.x;
    if (i == 0) g_count = 0;
    if (i < NENV * HID) g_h[0][i] = hxs[i];
}
__global__ void copy_hlast_kernel(float* __restrict__ dst) {
    int i = blockIdx.x * blockDim.x + threadIdx.x;
    if (i < NENV * HID) dst[i] = g_h[0][i];
}

// MODE 0 (A operand): [hi, hi, lo]   MODE 1 (B operand): [hi, lo, hi]
template <int MODE>
__global__ void split_bf16(const float* __restrict__ src,
                           __nv_bfloat16* __restrict__ dst, int total) {
    int i = blockIdx.x * blockDim.x + threadIdx.x;
    if (i >= total) return;
    int m = i >> 10;          // / HID
    int k = i & (HID - 1);
    float v = src[i];
    __nv_bfloat16 hi = __float2bfloat16(v);
    __nv_bfloat16 lo = __float2bfloat16(v - __bfloat162float(hi));
    __nv_bfloat16* row = dst + (size_t)m * GK;
    if (MODE == 0) { row[k] = hi; row[HID + k] = hi; row[2 * HID + k] = lo; }
    else           { row[k] = hi; row[HID + k] = lo; row[2 * HID + k] = hi; }
}

// ---------------- mma.sync bf16 GEMM: C[M,N] = A'[M,GK]*B'[N,GK]^T + bias ----------------
// CTA tile 128x128, BK=64 bf16 (128B rows, SW128), 3-stage cp.async pipeline.
// 8 warps in 4(m) x 2(n); warp tile 32x64; m16n8k16 fragments via ldmatrix.x4.
#define STG_BYTES 32768               // per stage: 16KB A + 16KB B
#define SM_GEMM   (3 * STG_BYTES)
#define NCHUNK    (GK / 64)           // 48

__device__ __forceinline__ void stage_issue(
    const __nv_bfloat16* __restrict__ A, const __nv_bfloat16* __restrict__ B,
    uint32_t smb, int s, int c, int m0, int n0, int tid)
{
#pragma unroll
    for (int q = 0; q < 4; q++) {
        int idx = q * 256 + tid;          // 0..1023
        int row = idx >> 3;               // 0..127
        int c16 = idx & 7;                // 16B chunk within 128B row
        uint32_t off = SWZ128(row * 128 + c16 * 16);
        const void* sA = (const void*)(A + (size_t)(m0 + row) * GK + c * 64 + c16 * 8);
        const void* sB = (const void*)(B + (size_t)(n0 + row) * GK + c * 64 + c16 * 8);
        CP16(smb + s * STG_BYTES + off, sA);
        CP16(smb + s * STG_BYTES + 16384 + off, sB);
    }
}

template <bool RELU>
__global__ __launch_bounds__(256) void gemm_mma(
    const __nv_bfloat16* __restrict__ A, const __nv_bfloat16* __restrict__ B,
    const float* __restrict__ bias, float* __restrict__ C, int N)
{
    extern __shared__ char smem[];
    const uint32_t smb = smem_u32(smem);
    const int tid  = threadIdx.x;
    const int warp = tid >> 5;
    const int lane = tid & 31;
    const int m0 = blockIdx.y * 128;
    const int n0 = blockIdx.x * 128;
    const int wm = warp >> 1;             // 0..3
    const int wn = warp & 1;              // 0..1

    // per-lane ldmatrix row bases (byte offsets within tile) + xor masks
    const int lrow = lane & 15;
    const int khi  = lane & 16;           // 0 or 16 bytes
    uint32_t a_rb[2], a_xm[2], b_rb[4], b_xm[4];
#pragma unroll
    for (int mi = 0; mi < 2; mi++) {
        int r = wm * 32 + mi * 16 + lrow;
        a_rb[mi] = r * 128;
        a_xm[mi] = (r << 4) & 0x70;
    }
#pragma unroll
    for (int nb = 0; nb < 4; nb++) {
        int r = wn * 64 + nb * 16 + lrow;
        b_rb[nb] = r * 128;
        b_xm[nb] = (r << 4) & 0x70;
    }

    float acc[2][8][4];
#pragma unroll
    for (int mi = 0; mi < 2; mi++)
#pragma unroll
        for (int ni = 0; ni < 8; ni++)
#pragma unroll
            for (int v = 0; v < 4; v++) acc[mi][ni][v] = 0.0f;

    stage_issue(A, B, smb, 0, 0, m0, n0, tid); CP_COMMIT();
    stage_issue(A, B, smb, 1, 1, m0, n0, tid); CP_COMMIT();
    stage_issue(A, B, smb, 2, 2, m0, n0, tid); CP_COMMIT();

    int s = 0;
    for (int c = 0; c < NCHUNK; c++) {
        CP_WAIT2();
        __syncthreads();
        const uint32_t sa = smb + s * STG_BYTES;
        const uint32_t sb = sa + 16384;

#pragma unroll
        for (int ks = 0; ks < 4; ks++) {
            const uint32_t col = ks * 32 + khi;
            uint32_t af[2][4];
#pragma unroll
            for (int mi = 0; mi < 2; mi++)
                LDSM4(af[mi][0], af[mi][1], af[mi][2], af[mi][3],
                      sa + a_rb[mi] + (col ^ a_xm[mi]));
            uint32_t bf_[4][4];
#pragma unroll
            for (int nb = 0; nb < 4; nb++)
                LDSM4(bf_[nb][0], bf_[nb][1], bf_[nb][2], bf_[nb][3],
                      sb + b_rb[nb] + (col ^ b_xm[nb]));
#pragma unroll
            for (int mi = 0; mi < 2; mi++)
#pragma unroll
                for (int nb = 0; nb < 4; nb++) {
                    MMA16816(acc[mi][nb * 2 + 0],
                             af[mi][0], af[mi][1], af[mi][2], af[mi][3],
                             bf_[nb][0], bf_[nb][2]);
                    MMA16816(acc[mi][nb * 2 + 1],
                             af[mi][0], af[mi][1], af[mi][2], af[mi][3],
                             bf_[nb][1], bf_[nb][3]);
                }
        }
        __syncthreads();
        if (c + 3 < NCHUNK)
            stage_issue(A, B, smb, s, c + 3, m0, n0, tid);
        CP_COMMIT();                      // one group per iter keeps wait_group math exact
        s = (s == 2) ? 0 : s + 1;
    }

    // epilogue: bias (+ReLU), fp32 stores
#pragma unroll
    for (int mi = 0; mi < 2; mi++) {
        const int r = m0 + wm * 32 + mi * 16 + (lane >> 2);
#pragma unroll
        for (int ni = 0; ni < 8; ni++) {
            const int col = n0 + wn * 64 + ni * 8 + 2 * (lane & 3);
            const float2 bv = *(const float2*)&bias[col];
            float2 v0, v1;
            v0.x = acc[mi][ni][0] + bv.x;  v0.y = acc[mi][ni][1] + bv.y;
            v1.x = acc[mi][ni][2] + bv.x;  v1.y = acc[mi][ni][3] + bv.y;
            if (RELU) {
                v0.x = fmaxf(v0.x, 0.f); v0.y = fmaxf(v0.y, 0.f);
                v1.x = fmaxf(v1.x, 0.f); v1.y = fmaxf(v1.y, 0.f);
            }
            *(float2*)&C[(size_t)r * N + col] = v0;
            *(float2*)&C[(size_t)(r + 8) * N + col] = v1;
        }
    }
}

// ---------------- persistent GRU scan (fp32, mask folded into epilogue) ----------------
__device__ __forceinline__ void load_h8(float4* pre, const float* __restrict__ h_in,
                                        int c, int tid) {
#pragma unroll
    for (int q = 0; q < 8; q++) {
        int idx = q * 256 + tid;
        int e = idx >> 5;
        int k4 = idx & 31;
        pre[q] = __ldcg((const float4*)&h_in[(size_t)e * HID + c * CK + k4 * 4]);
    }
}

__global__ __launch_bounds__(256) void scan_kernel(
    const float* __restrict__ done,
    const float* __restrict__ w_hh,
    const float* __restrict__ b_hh)
{
    extern __shared__ float sm[];
    float* w_sm = sm;                                  // 24 * WROW
    float* h_sm = sm + 3 * JPC * WROW;                 // 2 * 64 * HROW
    float* msk  = h_sm + 2 * 64 * HROW;                // 64

    const int tid   = threadIdx.x;
    const int warp  = tid >> 5;
    const int lane  = tid & 31;
    const int jgrp  = warp >> 2;                       // 0..1
    const int egrp  = warp & 3;                        // 0..3
    const int el    = lane & 15;
    const int jhalf = lane >> 4;
    const int env   = egrp * 16 + el;
    const int jl0   = jgrp * 4 + jhalf * 2;            // local j (even)
    const int jg0   = blockIdx.x * JPC + jl0;          // global j

#pragma unroll 4
    for (int r = 0; r < 3 * JPC; r++) {
        const float* src = &w_hh[(size_t)((r >> 3) * HID + blockIdx.x * JPC + (r & 7)) * HID];
        *(float4*)&w_sm[r * WROW + tid * 4] = *(const float4*)&src[tid * 4];
    }
    const float2 br2 = *(const float2*)&b_hh[jg0];
    const float2 bz2 = *(const float2*)&b_hh[HID + jg0];
    const float2 bn2 = *(const float2*)&b_hh[2 * HID + jg0];

    unsigned target = 0;

    for (int t = 0; t < TSTEPS; t++) {
        const int par = t & 1;
        const float* __restrict__ h_in  = g_h[par];
        float* __restrict__       h_out = g_h[par ^ 1];

        if (tid < 64) msk[tid] = 1.0f - done[t * NENV + tid];
        __syncthreads();

        const float* gib = g_gi + ((size_t)t * NENV + env) * HID3 + jg0;
        const float2 gir = __ldg((const float2*)(gib));
        const float2 giz = __ldg((const float2*)(gib + HID));
        const float2 gin = __ldg((const float2*)(gib + 2 * HID));
        const float2 hp  = __ldcg((const float2*)&h_in[(size_t)env * HID + jg0]);

        float4 pre[8];
        load_h8(pre, h_in, 0, tid);

        unsigned long long acc[2][3];
#pragma unroll
        for (int a = 0; a < 2; a++)
#pragma unroll
            for (int g = 0; g < 3; g++) acc[a][g] = 0ull;

        for (int c = 0; c < HID / CK; c++) {
            float* hb = h_sm + (c & 1) * 64 * HROW;
#pragma unroll
            for (int q = 0; q < 8; q++) {
                int idx = q * 256 + tid;
                *(float4*)&hb[(idx >> 5) * HROW + (idx & 31) * 4] = pre[q];
            }
            __syncthreads();
            if (c + 1 < HID / CK) load_h8(pre, h_in, c + 1, tid);

            const float* hr = hb + env * HROW;
            const float* w0 = w_sm + jl0 * WROW + c * CK;

#pragma unroll 8
            for (int ki = 0; ki < CK; ki += 4) {
                ulonglong2 H = *(const ulonglong2*)(hr + ki);
#pragma unroll
                for (int jl = 0; jl < 2; jl++) {
#pragma unroll
                    for (int g = 0; g < 3; g++) {
                        ulonglong2 W = *(const ulonglong2*)
                            (w0 + (g * JPC + jl) * WROW + ki);
                        fma2(acc[jl][g], H.x, W.x);
                        fma2(acc[jl][g], H.y, W.y);
                    }
                }
            }
            __syncthreads();
        }

        const float m = msk[env];
        float2 hv;
        {
            const float r = sigmoidf_(gir.x + m * lohi(acc[0][0]) + br2.x);
            const float z = sigmoidf_(giz.x + m * lohi(acc[0][1]) + bz2.x);
            const float n = tanhf(gin.x + r * (m * lohi(acc[0][2]) + bn2.x));
            hv.x = (1.0f - z) * n + z * (hp.x * m);
        }
        {
            const float r = sigmoidf_(gir.y + m * lohi(acc[1][0]) + br2.y);
            const float z = sigmoidf_(giz.y + m * lohi(acc[1][1]) + bz2.y);
            const float n = tanhf(gin.y + r * (m * lohi(acc[1][2]) + bn2.y));
            hv.y = (1.0f - z) * n + z * (hp.y * m);
        }
        __stcg((float2*)&h_out[(size_t)env * HID + jg0], hv);
        __stcg((float2*)&g_ys[((size_t)t * NENV + env) * HID + jg0], hv);

        // grid barrier
        __threadfence();
        __syncthreads();
        target += G;
        if (tid == 0) {
            atomicAdd(&g_count, 1u);
            while (*(volatile unsigned*)&g_count < target) __nanosleep(64);
            __threadfence();
        }
        __syncthreads();
    }
}

// ---------------- launch ----------------
extern "C" void kernel_launch(void* const* d_in, const int* in_sizes, int n_in,
                              void* d_out, int out_size)
{
    const float* x     = (const float*)d_in[0];
    const float* hxs   = (const float*)d_in[1];
    const float* done  = (const float*)d_in[2];
    const float* w_ih  = (const float*)d_in[3];
    const float* w_hh  = (const float*)d_in[4];
    const float* b_ih  = (const float*)d_in[5];
    const float* b_hh  = (const float*)d_in[6];
    const float* w_out = (const float*)d_in[7];
    const float* b_out = (const float*)d_in[8];
    float* out = (float*)d_out;

    float *gi_p = nullptr, *ys_p = nullptr;
    __nv_bfloat16 *bA = nullptr, *bB = nullptr;
    cudaGetSymbolAddress((void**)&gi_p, g_gi);
    cudaGetSymbolAddress((void**)&ys_p, g_ys);
    cudaGetSymbolAddress((void**)&bA, g_bufA);
    cudaGetSymbolAddress((void**)&bB, g_bufB);

    const int M = TSTEPS * NENV;   // 8192
    const int SMEM_SCAN = (3 * JPC * WROW + 2 * 64 * HROW + 64) * (int)sizeof(float);

    cudaFuncSetAttribute(scan_kernel,
                         cudaFuncAttributeMaxDynamicSharedMemorySize, SMEM_SCAN);
    cudaFuncSetAttribute(gemm_mma<false>,
                         cudaFuncAttributeMaxDynamicSharedMemorySize, SM_GEMM);
    cudaFuncSetAttribute(gemm_mma<true>,
                         cudaFuncAttributeMaxDynamicSharedMemorySize, SM_GEMM);

    init_kernel<<<(NENV * HID + 255) / 256, 256>>>(hxs);

    // gi = x @ w_ih^T + b_ih  via split-bf16 tensor GEMM
    split_bf16<0><<<(M * HID + 255) / 256, 256>>>(x, bA, M * HID);
    split_bf16<1><<<(HID3 * HID + 255) / 256, 256>>>(w_ih, bB, HID3 * HID);
    gemm_mma<false><<<dim3(HID3 / 128, M / 128), 256, SM_GEMM>>>(bA, bB, b_ih, gi_p, HID3);

    // 128-step persistent scan
    scan_kernel<<<G, 256, SMEM_SCAN>>>(done, w_hh, b_hh);

    // out = relu(ys @ w_out^T + b_out)
    split_bf16<0><<<(M * HID + 255) / 256, 256>>>(ys_p, bA, M * HID);
    split_bf16<1><<<(HID * HID + 255) / 256, 256>>>(w_out, bB, HID * HID);
    gemm_mma<true><<<dim3(HID / 128, M / 128), 256, SM_GEMM>>>(bA, bB, b_out, out, HID);

    copy_hlast_kernel<<<(NENV * HID + 255) / 256, 256>>>(out + (size_t)M * HID);
}

// round 5
// speedup vs baseline: 2.1095x; 2.1095x over previous
#include <cuda_runtime.h>
#include <cuda_bf16.h>
#include <math.h>
#include <stdint.h>

#define TSTEPS 128
#define NENV   64
#define HID    1024
#define HID3   (3 * HID)
#define GK     3072     // split-K concat (3 * HID)

#define G      128      // persistent scan CTAs
#define JPC    8        // j per CTA
#define CK     128      // h k-chunk staged in smem
#define HROW   132      // CK+4: (HROW mod 32)=4 words -> conflict-free consecutive-env lanes
#define WROW   1028

// ---------------- scratch ----------------
__device__ float g_gi[TSTEPS * NENV * HID3];            // 96 MB
__device__ float g_ys[TSTEPS * NENV * HID];             // 32 MB
__device__ float g_h[2][NENV * HID];
__device__ unsigned g_count;
__device__ __nv_bfloat16 g_bufA[TSTEPS * NENV * GK];    // 48 MB
__device__ __nv_bfloat16 g_bufB[HID3 * GK];             // 18 MB

// ---------------- ptx helpers (sm_103-safe) ----------------
__device__ __forceinline__ uint32_t smem_u32(const void* p) {
    uint32_t a;
    asm("{ .reg .u64 t; cvta.to.shared.u64 t, %1; cvt.u32.u64 %0, t; }" : "=r"(a) : "l"(p));
    return a;
}
#define SWZ128(x) ((x) ^ (((x) >> 3) & 0x70))

#define CP16(dst, src) \
    asm volatile("cp.async.cg.shared.global [%0], [%1], 16;" :: "r"(dst), "l"(src))
#define CP_COMMIT() asm volatile("cp.async.commit_group;" ::: "memory")
#define CP_WAIT2()  asm volatile("cp.async.wait_group 2;" ::: "memory")

#define LDSM4(r0, r1, r2, r3, addr) \
    asm volatile("ldmatrix.sync.aligned.m8n8.x4.shared.b16 {%0,%1,%2,%3}, [%4];" \
        : "=r"(r0), "=r"(r1), "=r"(r2), "=r"(r3) : "r"(addr))

#define MMA16816(d, a0, a1, a2, a3, b0, b1) \
    asm volatile("mma.sync.aligned.m16n8k16.row.col.f32.bf16.bf16.f32 " \
        "{%0,%1,%2,%3}, {%4,%5,%6,%7}, {%8,%9}, {%0,%1,%2,%3};" \
        : "+f"((d)[0]), "+f"((d)[1]), "+f"((d)[2]), "+f"((d)[3]) \
        : "r"(a0), "r"(a1), "r"(a2), "r"(a3), "r"(b0), "r"(b1))

// ---------------- misc ----------------
__device__ __forceinline__ float sigmoidf_(float x) { return 1.0f / (1.0f + expf(-x)); }
__device__ __forceinline__ void fma2(unsigned long long& c, unsigned long long a,
                                     unsigned long long b) {
    asm("fma.rn.f32x2 %0, %1, %2, %0;" : "+l"(c) : "l"(a), "l"(b));
}
__device__ __forceinline__ float lohi(unsigned long long v) {
    return __uint_as_float((unsigned)v) + __uint_as_float((unsigned)(v >> 32));
}

// ---------------- init / copy / split ----------------
__global__ void init_kernel(const float* __restrict__ hxs) {
    int i = blockIdx.x * blockDim.x + threadIdx.x;
    if (i == 0) g_count = 0;
    if (i < NENV * HID) g_h[0][i] = hxs[i];
}
__global__ void copy_hlast_kernel(float* __restrict__ dst) {
    int i = blockIdx.x * blockDim.x + threadIdx.x;
    if (i < NENV * HID) dst[i] = g_h[0][i];
}

// MODE 0 (A operand): [hi, hi, lo]   MODE 1 (B operand): [hi, lo, hi]
template <int MODE>
__global__ void split_bf16(const float* __restrict__ src,
                           __nv_bfloat16* __restrict__ dst, int total) {
    int i = blockIdx.x * blockDim.x + threadIdx.x;
    if (i >= total) return;
    int m = i >> 10;
    int k = i & (HID - 1);
    float v = src[i];
    __nv_bfloat16 hi = __float2bfloat16(v);
    __nv_bfloat16 lo = __float2bfloat16(v - __bfloat162float(hi));
    __nv_bfloat16* row = dst + (size_t)m * GK;
    if (MODE == 0) { row[k] = hi; row[HID + k] = hi; row[2 * HID + k] = lo; }
    else           { row[k] = hi; row[HID + k] = lo; row[2 * HID + k] = hi; }
}

// ---------------- mma.sync bf16 GEMM (unchanged from R4 — measured win) ----------------
#define STG_BYTES 32768
#define SM_GEMM   (3 * STG_BYTES)
#define NCHUNK    (GK / 64)

__device__ __forceinline__ void stage_issue(
    const __nv_bfloat16* __restrict__ A, const __nv_bfloat16* __restrict__ B,
    uint32_t smb, int s, int c, int m0, int n0, int tid)
{
#pragma unroll
    for (int q = 0; q < 4; q++) {
        int idx = q * 256 + tid;
        int row = idx >> 3;
        int c16 = idx & 7;
        uint32_t off = SWZ128(row * 128 + c16 * 16);
        const void* sA = (const void*)(A + (size_t)(m0 + row) * GK + c * 64 + c16 * 8);
        const void* sB = (const void*)(B + (size_t)(n0 + row) * GK + c * 64 + c16 * 8);
        CP16(smb + s * STG_BYTES + off, sA);
        CP16(smb + s * STG_BYTES + 16384 + off, sB);
    }
}

template <bool RELU>
__global__ __launch_bounds__(256) void gemm_mma(
    const __nv_bfloat16* __restrict__ A, const __nv_bfloat16* __restrict__ B,
    const float* __restrict__ bias, float* __restrict__ C, int N)
{
    extern __shared__ char smem[];
    const uint32_t smb = smem_u32(smem);
    const int tid  = threadIdx.x;
    const int warp = tid >> 5;
    const int lane = tid & 31;
    const int m0 = blockIdx.y * 128;
    const int n0 = blockIdx.x * 128;
    const int wm = warp >> 1;
    const int wn = warp & 1;

    const int lrow = lane & 15;
    const int khi  = lane & 16;
    uint32_t a_rb[2], a_xm[2], b_rb[4], b_xm[4];
#pragma unroll
    for (int mi = 0; mi < 2; mi++) {
        int r = wm * 32 + mi * 16 + lrow;
        a_rb[mi] = r * 128;
        a_xm[mi] = (r << 4) & 0x70;
    }
#pragma unroll
    for (int nb = 0; nb < 4; nb++) {
        int r = wn * 64 + nb * 16 + lrow;
        b_rb[nb] = r * 128;
        b_xm[nb] = (r << 4) & 0x70;
    }

    float acc[2][8][4];
#pragma unroll
    for (int mi = 0; mi < 2; mi++)
#pragma unroll
        for (int ni = 0; ni < 8; ni++)
#pragma unroll
            for (int v = 0; v < 4; v++) acc[mi][ni][v] = 0.0f;

    stage_issue(A, B, smb, 0, 0, m0, n0, tid); CP_COMMIT();
    stage_issue(A, B, smb, 1, 1, m0, n0, tid); CP_COMMIT();
    stage_issue(A, B, smb, 2, 2, m0, n0, tid); CP_COMMIT();

    int s = 0;
    for (int c = 0; c < NCHUNK; c++) {
        CP_WAIT2();
        __syncthreads();
        const uint32_t sa = smb + s * STG_BYTES;
        const uint32_t sb = sa + 16384;

#pragma unroll
        for (int ks = 0; ks < 4; ks++) {
            const uint32_t col = ks * 32 + khi;
            uint32_t af[2][4];
#pragma unroll
            for (int mi = 0; mi < 2; mi++)
                LDSM4(af[mi][0], af[mi][1], af[mi][2], af[mi][3],
                      sa + a_rb[mi] + (col ^ a_xm[mi]));
            uint32_t bf_[4][4];
#pragma unroll
            for (int nb = 0; nb < 4; nb++)
                LDSM4(bf_[nb][0], bf_[nb][1], bf_[nb][2], bf_[nb][3],
                      sb + b_rb[nb] + (col ^ b_xm[nb]));
#pragma unroll
            for (int mi = 0; mi < 2; mi++)
#pragma unroll
                for (int nb = 0; nb < 4; nb++) {
                    MMA16816(acc[mi][nb * 2 + 0],
                             af[mi][0], af[mi][1], af[mi][2], af[mi][3],
                             bf_[nb][0], bf_[nb][2]);
                    MMA16816(acc[mi][nb * 2 + 1],
                             af[mi][0], af[mi][1], af[mi][2], af[mi][3],
                             bf_[nb][1], bf_[nb][3]);
                }
        }
        __syncthreads();
        if (c + 3 < NCHUNK)
            stage_issue(A, B, smb, s, c + 3, m0, n0, tid);
        CP_COMMIT();
        s = (s == 2) ? 0 : s + 1;
    }

#pragma unroll
    for (int mi = 0; mi < 2; mi++) {
        const int r = m0 + wm * 32 + mi * 16 + (lane >> 2);
#pragma unroll
        for (int ni = 0; ni < 8; ni++) {
            const int col = n0 + wn * 64 + ni * 8 + 2 * (lane & 3);
            const float2 bv = *(const float2*)&bias[col];
            float2 v0, v1;
            v0.x = acc[mi][ni][0] + bv.x;  v0.y = acc[mi][ni][1] + bv.y;
            v1.x = acc[mi][ni][2] + bv.x;  v1.y = acc[mi][ni][3] + bv.y;
            if (RELU) {
                v0.x = fmaxf(v0.x, 0.f); v0.y = fmaxf(v0.y, 0.f);
                v1.x = fmaxf(v1.x, 0.f); v1.y = fmaxf(v1.y, 0.f);
            }
            *(float2*)&C[(size_t)r * N + col] = v0;
            *(float2*)&C[(size_t)(r + 8) * N + col] = v1;
        }
    }
}

// ---------------- persistent GRU scan: 8 pairs/thread, k-split, smem reduction ----------------
// kq = tid>>6 (k sub-window of 32 within each 128-k staged chunk)
// grp = tid&63: jp = grp>>4 (j-pair jl0=2*jp), e0 = grp&15 -> envs e0+16i, i=0..3
// Per thread: 8 (env,j) pairs x 3 gates = 24 ull accumulators.
__device__ __forceinline__ void load_h8(float4* pre, const float* __restrict__ h_in,
                                        int c, int tid) {
#pragma unroll
    for (int q = 0; q < 8; q++) {
        int idx = q * 256 + tid;
        int e = idx >> 5;
        int k4 = idx & 31;
        pre[q] = __ldcg((const float4*)&h_in[(size_t)e * HID + c * CK + k4 * 4]);
    }
}

__global__ __launch_bounds__(256) void scan_kernel(
    const float* __restrict__ done,
    const float* __restrict__ w_hh,
    const float* __restrict__ b_hh)
{
    extern __shared__ float sm[];
    float* w_sm = sm;                                  // 24 * WROW floats
    float* h_sm = sm + 3 * JPC * WROW;                 // 2 * 64 * HROW floats
    float* msk  = h_sm + 2 * 64 * HROW;                // 64
    float* red  = h_sm;                                // reduction buf aliases h staging (24*256 floats)

    const int tid = threadIdx.x;
    const int kq  = tid >> 6;                          // 0..3
    const int grp = tid & 63;
    const int jp  = grp >> 4;                          // 0..3
    const int e0  = grp & 15;
    const int jl0 = jp * 2;

    // epilogue mapping: this thread finalizes pairs (eenv, ejl0) and (eenv, ejl0+1)
    const int eenv = tid & 63;
    const int ejl0 = (tid >> 6) * 2;
    const int ejg0 = blockIdx.x * JPC + ejl0;
    const int egrpE = (ejl0 >> 1) * 16 + (eenv & 15);  // grp owning these pairs
    const int epbase = (eenv >> 4) * 2;                // pair index base (p = epbase + jj)

    // cache w_hh slice
#pragma unroll 4
    for (int r = 0; r < 3 * JPC; r++) {
        const float* src = &w_hh[(size_t)((r >> 3) * HID + blockIdx.x * JPC + (r & 7)) * HID];
        *(float4*)&w_sm[r * WROW + tid * 4] = *(const float4*)&src[tid * 4];
    }
    const float2 br2 = *(const float2*)&b_hh[ejg0];
    const float2 bz2 = *(const float2*)&b_hh[HID + ejg0];
    const float2 bn2 = *(const float2*)&b_hh[2 * HID + ejg0];

    unsigned target = 0;

    for (int t = 0; t < TSTEPS; t++) {
        const int par = t & 1;
        const float* __restrict__ h_in  = g_h[par];
        float* __restrict__       h_out = g_h[par ^ 1];

        if (tid < 64) msk[tid] = 1.0f - done[t * NENV + tid];
        __syncthreads();

        // epilogue operand prefetch (latency hidden under K loop)
        const float* gib = g_gi + ((size_t)t * NENV + eenv) * HID3 + ejg0;
        const float2 gir = __ldg((const float2*)(gib));
        const float2 giz = __ldg((const float2*)(gib + HID));
        const float2 gin = __ldg((const float2*)(gib + 2 * HID));
        const float2 hp  = __ldcg((const float2*)&h_in[(size_t)eenv * HID + ejg0]);

        float4 pre[8];
        load_h8(pre, h_in, 0, tid);

        unsigned long long acc[8][3];
#pragma unroll
        for (int p = 0; p < 8; p++)
#pragma unroll
            for (int g = 0; g < 3; g++) acc[p][g] = 0ull;

        for (int c = 0; c < HID / CK; c++) {
            float* hb = h_sm + (c & 1) * 64 * HROW;
#pragma unroll
            for (int q = 0; q < 8; q++) {
                int idx = q * 256 + tid;
                *(float4*)&hb[(idx >> 5) * HROW + (idx & 31) * 4] = pre[q];
            }
            __syncthreads();
            if (c + 1 < HID / CK) load_h8(pre, h_in, c + 1, tid);

            const float* hB = hb + kq * 32;
            const float* wB = w_sm + c * CK + kq * 32;

#pragma unroll
            for (int ki = 0; ki < 32; ki += 4) {
                ulonglong2 H[4];
#pragma unroll
                for (int i = 0; i < 4; i++)
                    H[i] = *(const ulonglong2*)(hB + (e0 + 16 * i) * HROW + ki);
#pragma unroll
                for (int jj = 0; jj < 2; jj++) {
#pragma unroll
                    for (int g = 0; g < 3; g++) {
                        ulonglong2 W = *(const ulonglong2*)
                            (wB + (g * JPC + jl0 + jj) * WROW + ki);
#pragma unroll
                        for (int i = 0; i < 4; i++) {
                            fma2(acc[i * 2 + jj][g], H[i].x, W.x);
                            fma2(acc[i * 2 + jj][g], H[i].y, W.y);
                        }
                    }
                }
            }
            __syncthreads();
        }

        // cross-kq reduction: collapse accs to floats, lane-contiguous smem layout
#pragma unroll
        for (int p = 0; p < 8; p++)
#pragma unroll
            for (int g = 0; g < 3; g++)
                red[(p * 3 + g) * 256 + tid] = lohi(acc[p][g]);
        __syncthreads();

        const float m = msk[eenv];
        float2 hv;
#pragma unroll
        for (int jj = 0; jj < 2; jj++) {
            float a[3];
#pragma unroll
            for (int g = 0; g < 3; g++) {
                const float* rp = &red[((epbase + jj) * 3 + g) * 256 + egrpE];
                a[g] = (rp[0] + rp[64]) + (rp[128] + rp[192]);
            }
            const float bR = jj ? br2.y : br2.x;
            const float bZ = jj ? bz2.y : bz2.x;
            const float bN = jj ? bn2.y : bn2.x;
            const float giR = jj ? gir.y : gir.x;
            const float giZ = jj ? giz.y : giz.x;
            const float giN = jj ? gin.y : gin.x;
            const float hP  = (jj ? hp.y : hp.x) * m;
            const float r = sigmoidf_(giR + m * a[0] + bR);
            const float z = sigmoidf_(giZ + m * a[1] + bZ);
            const float n = tanhf(giN + r * (m * a[2] + bN));
            const float hn = (1.0f - z) * n + z * hP;
            if (jj) hv.y = hn; else hv.x = hn;
        }
        __stcg((float2*)&h_out[(size_t)eenv * HID + ejg0], hv);
        __stcg((float2*)&g_ys[((size_t)t * NENV + eenv) * HID + ejg0], hv);

        // grid barrier
        __threadfence();
        __syncthreads();
        target += G;
        if (tid == 0) {
            atomicAdd(&g_count, 1u);
            while (*(volatile unsigned*)&g_count < target) __nanosleep(64);
            __threadfence();
        }
        __syncthreads();
    }
}

// ---------------- launch ----------------
extern "C" void kernel_launch(void* const* d_in, const int* in_sizes, int n_in,
                              void* d_out, int out_size)
{
    const float* x     = (const float*)d_in[0];
    const float* hxs   = (const float*)d_in[1];
    const float* done  = (const float*)d_in[2];
    const float* w_ih  = (const float*)d_in[3];
    const float* w_hh  = (const float*)d_in[4];
    const float* b_ih  = (const float*)d_in[5];
    const float* b_hh  = (const float*)d_in[6];
    const float* w_out = (const float*)d_in[7];
    const float* b_out = (const float*)d_in[8];
    float* out = (float*)d_out;

    float *gi_p = nullptr, *ys_p = nullptr;
    __nv_bfloat16 *bA = nullptr, *bB = nullptr;
    cudaGetSymbolAddress((void**)&gi_p, g_gi);
    cudaGetSymbolAddress((void**)&ys_p, g_ys);
    cudaGetSymbolAddress((void**)&bA, g_bufA);
    cudaGetSymbolAddress((void**)&bB, g_bufB);

    const int M = TSTEPS * NENV;   // 8192
    const int SMEM_SCAN = (3 * JPC * WROW + 2 * 64 * HROW + 64) * (int)sizeof(float);

    cudaFuncSetAttribute(scan_kernel,
                         cudaFuncAttributeMaxDynamicSharedMemorySize, SMEM_SCAN);
    cudaFuncSetAttribute(gemm_mma<false>,
                         cudaFuncAttributeMaxDynamicSharedMemorySize, SM_GEMM);
    cudaFuncSetAttribute(gemm_mma<true>,
                         cudaFuncAttributeMaxDynamicSharedMemorySize, SM_GEMM);

    init_kernel<<<(NENV * HID + 255) / 256, 256>>>(hxs);

    // gi = x @ w_ih^T + b_ih  via split-bf16 tensor GEMM
    split_bf16<0><<<(M * HID + 255) / 256, 256>>>(x, bA, M * HID);
    split_bf16<1><<<(HID3 * HID + 255) / 256, 256>>>(w_ih, bB, HID3 * HID);
    gemm_mma<false><<<dim3(HID3 / 128, M / 128), 256, SM_GEMM>>>(bA, bB, b_ih, gi_p, HID3);

    // 128-step persistent scan
    scan_kernel<<<G, 256, SMEM_SCAN>>>(done, w_hh, b_hh);

    // out = relu(ys @ w_out^T + b_out)
    split_bf16<0><<<(M * HID + 255) / 256, 256>>>(ys_p, bA, M * HID);
    split_bf16<1><<<(HID * HID + 255) / 256, 256>>>(w_out, bB, HID * HID);
    gemm_mma<true><<<dim3(HID / 128, M / 128), 256, SM_GEMM>>>(bA, bB, b_out, out, HID);

    copy_hlast_kernel<<<(NENV * HID + 255) / 256, 256>>>(out + (size_t)M * HID);
}